// round 1
// baseline (speedup 1.0000x reference)
#include <cuda_runtime.h>
#include <cuda_bf16.h>
#include <cstddef>

// MultiNetworkRNN: N_NET=32, N_UNITS=2048, N_EXC=1638, N_INH=410
// out[n,q] = r + DT*((-r + relu(total))/TAU)
// total[:,0:NE]  = r_e @ W_ee + r_i @ W_ie + unit_input_e          (einsum 'npq,np->nq')
// total[:,NE:NU] = r_e @ W_ei + r_i @ W_ii + unit_input_i + inter
// inter[i,a] = sum_{j,b} W_inter[i,j,a,b] * r_i[i,b]

#define N_NET 32
#define NU 2048
#define NE 1638
#define NI 410
#define DT 0.01f
#define TAU 0.1f

__device__ float g_inter[N_NET * NI];

// ---------------------------------------------------------------------------
// Kernel 1: inter[i,a] = sum_{j,b} W_inter[i,j,a,b] * r[i, NE+b]
// One block per (a, i). 13120 blocks x 128 threads. All strides even -> float2 ok.
// ---------------------------------------------------------------------------
__global__ void __launch_bounds__(128) inter_kernel(
    const float* __restrict__ r,
    const float* __restrict__ W_inter)
{
    __shared__ float rs[NI];
    __shared__ float red[4];

    const int a   = blockIdx.x;
    const int i   = blockIdx.y;
    const int tid = threadIdx.x;

    const float* ri = r + (size_t)i * NU + NE;
    for (int b = tid; b < NI; b += 128) rs[b] = ri[b];
    __syncthreads();

    // base of W_inter[i, 0, a, 0]
    const float* base = W_inter + (size_t)i * N_NET * (NI * NI) + (size_t)a * NI;

    float acc = 0.f;
    // loop order: t outer, j inner (unrolled) -> 8 independent LDG.64 in flight
    for (int t = tid; t < NI / 2; t += 128) {
        const float x = rs[2 * t];
        const float y = rs[2 * t + 1];
        #pragma unroll 8
        for (int j = 0; j < N_NET; ++j) {
            const float2 w = *(const float2*)(base + (size_t)j * (NI * NI) + 2 * t);
            acc = fmaf(w.x, x, acc);
            acc = fmaf(w.y, y, acc);
        }
    }

    // block reduce (128 -> 1)
    #pragma unroll
    for (int o = 16; o > 0; o >>= 1)
        acc += __shfl_down_sync(0xFFFFFFFFu, acc, o);
    if ((tid & 31) == 0) red[tid >> 5] = acc;
    __syncthreads();
    if (tid == 0)
        g_inter[i * NI + a] = red[0] + red[1] + red[2] + red[3];
}

// ---------------------------------------------------------------------------
// Kernel 2: all four GEMVs + epilogue. Grid (16 tiles, 32 nets), 64 threads.
// Each thread owns q-pair (q, q+1): float2 loads (all strides even -> aligned).
// NE=1638 is even, so a pair never straddles the exc/inh boundary.
// ---------------------------------------------------------------------------
__global__ void __launch_bounds__(64) main_kernel(
    const float* __restrict__ unit_input,
    const float* __restrict__ r,
    const float* __restrict__ W_ee,
    const float* __restrict__ W_ei,
    const float* __restrict__ W_ie,
    const float* __restrict__ W_ii,
    float* __restrict__ out)
{
    __shared__ float rs[NU];

    const int n   = blockIdx.y;
    const int tid = threadIdx.x;
    const int q   = blockIdx.x * 128 + 2 * tid;   // q in [0, 2048), even

    const float* rn = r + (size_t)n * NU;
    for (int i = tid; i < NU; i += 64) rs[i] = rn[i];
    __syncthreads();

    float a0 = 0.f, a1 = 0.f, b0 = 0.f, b1 = 0.f;

    if (q < NE) {
        // excitatory output: W_ee (NE rows, width NE) + W_ie (NI rows, width NE)
        const float* pee = W_ee + (size_t)n * NE * NE + q;
        #pragma unroll 4
        for (int p = 0; p < NE; p += 2) {
            const float2 w0 = *(const float2*)(pee + (size_t)p * NE);
            const float2 w1 = *(const float2*)(pee + (size_t)(p + 1) * NE);
            a0 = fmaf(rs[p],     w0.x, a0);
            a1 = fmaf(rs[p],     w0.y, a1);
            b0 = fmaf(rs[p + 1], w1.x, b0);
            b1 = fmaf(rs[p + 1], w1.y, b1);
        }
        const float* pie = W_ie + (size_t)n * NI * NE + q;
        #pragma unroll 4
        for (int p = 0; p < NI; p += 2) {
            const float2 w0 = *(const float2*)(pie + (size_t)p * NE);
            const float2 w1 = *(const float2*)(pie + (size_t)(p + 1) * NE);
            a0 = fmaf(rs[NE + p],     w0.x, a0);
            a1 = fmaf(rs[NE + p],     w0.y, a1);
            b0 = fmaf(rs[NE + p + 1], w1.x, b0);
            b1 = fmaf(rs[NE + p + 1], w1.y, b1);
        }
        a0 += unit_input[(size_t)n * NU + q];
        a1 += unit_input[(size_t)n * NU + q + 1];
    } else {
        // inhibitory output: W_ei (NE rows, width NI) + W_ii (NI rows, width NI)
        const int qq = q - NE;  // even
        const float* pei = W_ei + (size_t)n * NE * NI + qq;
        #pragma unroll 4
        for (int p = 0; p < NE; p += 2) {
            const float2 w0 = *(const float2*)(pei + (size_t)p * NI);
            const float2 w1 = *(const float2*)(pei + (size_t)(p + 1) * NI);
            a0 = fmaf(rs[p],     w0.x, a0);
            a1 = fmaf(rs[p],     w0.y, a1);
            b0 = fmaf(rs[p + 1], w1.x, b0);
            b1 = fmaf(rs[p + 1], w1.y, b1);
        }
        const float* pii = W_ii + (size_t)n * NI * NI + qq;
        #pragma unroll 4
        for (int p = 0; p < NI; p += 2) {
            const float2 w0 = *(const float2*)(pii + (size_t)p * NI);
            const float2 w1 = *(const float2*)(pii + (size_t)(p + 1) * NI);
            a0 = fmaf(rs[NE + p],     w0.x, a0);
            a1 = fmaf(rs[NE + p],     w0.y, a1);
            b0 = fmaf(rs[NE + p + 1], w1.x, b0);
            b1 = fmaf(rs[NE + p + 1], w1.y, b1);
        }
        a0 += unit_input[(size_t)n * NU + q]     + g_inter[n * NI + qq];
        a1 += unit_input[(size_t)n * NU + q + 1] + g_inter[n * NI + qq + 1];
    }

    const float t0 = a0 + b0;
    const float t1 = a1 + b1;
    const float phi0 = fmaxf(t0, 0.f);
    const float phi1 = fmaxf(t1, 0.f);
    const float r0 = rs[q];
    const float r1 = rs[q + 1];
    out[(size_t)n * NU + q]     = r0 + DT * ((phi0 - r0) / TAU);
    out[(size_t)n * NU + q + 1] = r1 + DT * ((phi1 - r1) / TAU);
}

extern "C" void kernel_launch(void* const* d_in, const int* in_sizes, int n_in,
                              void* d_out, int out_size)
{
    const float* unit_input = (const float*)d_in[0];
    const float* r          = (const float*)d_in[1];
    const float* W_ee       = (const float*)d_in[2];
    const float* W_ei       = (const float*)d_in[3];
    const float* W_ie       = (const float*)d_in[4];
    const float* W_ii       = (const float*)d_in[5];
    const float* W_inter    = (const float*)d_in[6];
    float* out = (float*)d_out;

    inter_kernel<<<dim3(NI, N_NET), 128>>>(r, W_inter);
    main_kernel<<<dim3(16, N_NET), 64>>>(unit_input, r, W_ee, W_ei, W_ie, W_ii, out);
}

// round 2
// speedup vs baseline: 2.6505x; 2.6505x over previous
#include <cuda_runtime.h>
#include <cuda_bf16.h>
#include <cstddef>

// MultiNetworkRNN: N_NET=32, N_UNITS=2048, N_EXC=1638, N_INH=410
// out[n,q] = r + DT*((relu(total)-r)/TAU)
// total[:,0:NE]  = r_e @ W_ee + r_i @ W_ie + unit_input_e
// total[:,NE:NU] = r_e @ W_ei + r_i @ W_ii + unit_input_i + inter
// inter[i,a] = sum_{j,b} W_inter[i,j,a,b] * r[i, NE+b]

#define N_NET 32
#define NU 2048
#define NE 1638
#define NI 410
#define DT 0.01f
#define TAU 0.1f

#define P_SLICES 8
#define P_PER_SLICE (NU / P_SLICES)   // 256

__device__ float g_inter[N_NET * NI];
__device__ float g_partial[P_SLICES * N_NET * NU];   // [slice][net][q], 2 MB

// ---------------------------------------------------------------------------
// Kernel 1: inter[i,a] = sum_{j,b} W_inter[i,j,a,b] * r[i, NE+b]
// One block per (a, i). Already measured at ~6.8 TB/s — unchanged.
// ---------------------------------------------------------------------------
__global__ void __launch_bounds__(128) inter_kernel(
    const float* __restrict__ r,
    const float* __restrict__ W_inter)
{
    __shared__ float rs[NI];
    __shared__ float red[4];

    const int a   = blockIdx.x;
    const int i   = blockIdx.y;
    const int tid = threadIdx.x;

    const float* ri = r + (size_t)i * NU + NE;
    for (int b = tid; b < NI; b += 128) rs[b] = ri[b];
    __syncthreads();

    const float* base = W_inter + (size_t)i * N_NET * (NI * NI) + (size_t)a * NI;

    float acc = 0.f;
    for (int t = tid; t < NI / 2; t += 128) {
        const float x = rs[2 * t];
        const float y = rs[2 * t + 1];
        #pragma unroll 8
        for (int j = 0; j < N_NET; ++j) {
            const float2 w = *(const float2*)(base + (size_t)j * (NI * NI) + 2 * t);
            acc = fmaf(w.x, x, acc);
            acc = fmaf(w.y, y, acc);
        }
    }

    #pragma unroll
    for (int o = 16; o > 0; o >>= 1)
        acc += __shfl_down_sync(0xFFFFFFFFu, acc, o);
    if ((tid & 31) == 0) red[tid >> 5] = acc;
    __syncthreads();
    if (tid == 0)
        g_inter[i * NI + a] = red[0] + red[1] + red[2] + red[3];
}

// ---------------------------------------------------------------------------
// Kernel 2: partial GEMV sums. Grid (16 q-tiles, 8 p-slices, 32 nets) = 4096
// blocks x 128 threads. Each thread owns one q column, sums its 256-row
// p-slice with explicit 8-deep load batching (8 LDGs in flight per thread).
// Warp reads 128 contiguous columns per row -> fully coalesced 512B lines.
// ---------------------------------------------------------------------------
__global__ void __launch_bounds__(128) partial_kernel(
    const float* __restrict__ r,
    const float* __restrict__ W_ee,
    const float* __restrict__ W_ei,
    const float* __restrict__ W_ie,
    const float* __restrict__ W_ii)
{
    __shared__ float rs[P_PER_SLICE];

    const int tid = threadIdx.x;
    const int q   = blockIdx.x * 128 + tid;     // 0..2047
    const int ps  = blockIdx.y;                 // p slice
    const int n   = blockIdx.z;                 // net

    const int pa = ps * P_PER_SLICE;
    const int pb = pa + P_PER_SLICE;

    // stage this slice of r into shared
    rs[tid]       = r[(size_t)n * NU + pa + tid];
    rs[tid + 128] = r[(size_t)n * NU + pa + tid + 128];
    __syncthreads();

    // per-thread column pointers into the E-row block (p<NE) and I-row block
    const float* colE;
    const float* colI;
    int stride;
    if (q < NE) {
        stride = NE;
        colE = W_ee + (size_t)n * NE * NE + q;
        colI = W_ie + (size_t)n * NI * NE + q;
    } else {
        const int qq = q - NE;
        stride = NI;
        colE = W_ei + (size_t)n * NE * NI + qq;
        colI = W_ii + (size_t)n * NI * NI + qq;
    }

    float acc = 0.f;

    // --- rows p in [pa, min(pb, NE)) come from the E-row matrix ---
    {
        const int pe = (pb < NE) ? pb : NE;
        int p = pa;
        for (; p + 8 <= pe; p += 8) {
            const float w0 = colE[(size_t)(p + 0) * stride];
            const float w1 = colE[(size_t)(p + 1) * stride];
            const float w2 = colE[(size_t)(p + 2) * stride];
            const float w3 = colE[(size_t)(p + 3) * stride];
            const float w4 = colE[(size_t)(p + 4) * stride];
            const float w5 = colE[(size_t)(p + 5) * stride];
            const float w6 = colE[(size_t)(p + 6) * stride];
            const float w7 = colE[(size_t)(p + 7) * stride];
            const int t = p - pa;
            acc = fmaf(w0, rs[t + 0], acc);
            acc = fmaf(w1, rs[t + 1], acc);
            acc = fmaf(w2, rs[t + 2], acc);
            acc = fmaf(w3, rs[t + 3], acc);
            acc = fmaf(w4, rs[t + 4], acc);
            acc = fmaf(w5, rs[t + 5], acc);
            acc = fmaf(w6, rs[t + 6], acc);
            acc = fmaf(w7, rs[t + 7], acc);
        }
        for (; p < pe; ++p)
            acc = fmaf(colE[(size_t)p * stride], rs[p - pa], acc);
    }

    // --- rows p in [max(pa, NE), pb) come from the I-row matrix ---
    {
        const int p0 = (pa > NE) ? pa : NE;
        int p = p0;
        for (; p + 8 <= pb; p += 8) {
            const float w0 = colI[(size_t)(p - NE + 0) * stride];
            const float w1 = colI[(size_t)(p - NE + 1) * stride];
            const float w2 = colI[(size_t)(p - NE + 2) * stride];
            const float w3 = colI[(size_t)(p - NE + 3) * stride];
            const float w4 = colI[(size_t)(p - NE + 4) * stride];
            const float w5 = colI[(size_t)(p - NE + 5) * stride];
            const float w6 = colI[(size_t)(p - NE + 6) * stride];
            const float w7 = colI[(size_t)(p - NE + 7) * stride];
            const int t = p - pa;
            acc = fmaf(w0, rs[t + 0], acc);
            acc = fmaf(w1, rs[t + 1], acc);
            acc = fmaf(w2, rs[t + 2], acc);
            acc = fmaf(w3, rs[t + 3], acc);
            acc = fmaf(w4, rs[t + 4], acc);
            acc = fmaf(w5, rs[t + 5], acc);
            acc = fmaf(w6, rs[t + 6], acc);
            acc = fmaf(w7, rs[t + 7], acc);
        }
        for (; p < pb; ++p)
            acc = fmaf(colI[(size_t)(p - NE) * stride], rs[p - pa], acc);
    }

    g_partial[((size_t)ps * N_NET + n) * NU + q] = acc;
}

// ---------------------------------------------------------------------------
// Kernel 3: reduce 8 partials + unit_input (+inter for inhibitory) + epilogue.
// 32*2048 outputs, 64 blocks x 1024 threads.
// ---------------------------------------------------------------------------
__global__ void __launch_bounds__(1024) reduce_kernel(
    const float* __restrict__ unit_input,
    const float* __restrict__ r,
    float* __restrict__ out)
{
    const int idx = blockIdx.x * 1024 + threadIdx.x;   // 0..65535
    const int n = idx >> 11;          // / 2048
    const int q = idx & 2047;

    float acc = 0.f;
    #pragma unroll
    for (int s = 0; s < P_SLICES; ++s)
        acc += g_partial[((size_t)s * N_NET + n) * NU + q];

    acc += unit_input[idx];
    if (q >= NE) acc += g_inter[n * NI + (q - NE)];

    const float rv  = r[idx];
    const float phi = fmaxf(acc, 0.f);
    out[idx] = rv + DT * ((phi - rv) / TAU);
}

extern "C" void kernel_launch(void* const* d_in, const int* in_sizes, int n_in,
                              void* d_out, int out_size)
{
    const float* unit_input = (const float*)d_in[0];
    const float* r          = (const float*)d_in[1];
    const float* W_ee       = (const float*)d_in[2];
    const float* W_ei       = (const float*)d_in[3];
    const float* W_ie       = (const float*)d_in[4];
    const float* W_ii       = (const float*)d_in[5];
    const float* W_inter    = (const float*)d_in[6];
    float* out = (float*)d_out;

    inter_kernel<<<dim3(NI, N_NET), 128>>>(r, W_inter);
    partial_kernel<<<dim3(16, P_SLICES, N_NET), 128>>>(r, W_ee, W_ei, W_ie, W_ii);
    reduce_kernel<<<64, 1024>>>(unit_input, r, out);
}

// round 3
// speedup vs baseline: 2.7714x; 1.0456x over previous
#include <cuda_runtime.h>
#include <cuda_bf16.h>
#include <cstddef>

// MultiNetworkRNN: N_NET=32, N_UNITS=2048, N_EXC=1638, N_INH=410
// out[n,q] = r + DT*((relu(total)-r)/TAU)
// total[:,0:NE]  = r_e @ W_ee + r_i @ W_ie + unit_input_e
// total[:,NE:NU] = r_e @ W_ei + r_i @ W_ii + unit_input_i + inter
// inter[i,a] = sum_{j,b} W_inter[i,j,a,b] * r[i, NE+b]

#define N_NET 32
#define NU 2048
#define NE 1638
#define NI 410
#define DT 0.01f
#define TAU 0.1f

#define P_SLICES 8
#define P_PER_SLICE (NU / P_SLICES)     // 256

#define INTER_BLOCKS (N_NET * NI)       // 13120
#define PARTIAL_BLOCKS (16 * P_SLICES * N_NET)  // 4096
#define TOTAL_BLOCKS (INTER_BLOCKS + PARTIAL_BLOCKS)

__device__ float g_inter[N_NET * NI];
__device__ float g_partial[P_SLICES * N_NET * NU];   // [slice][net][q], 2 MB

// ---------------------------------------------------------------------------
// Fused kernel: blocks [0, INTER_BLOCKS) compute inter[i,a];
// blocks [INTER_BLOCKS, TOTAL_BLOCKS) compute partial GEMV sums.
// Both roles are independent DRAM streams; fusing removes the kernel
// boundary + tail-wave DRAM drain between them.
// ---------------------------------------------------------------------------
__global__ void __launch_bounds__(128) fused_kernel(
    const float* __restrict__ r,
    const float* __restrict__ W_ee,
    const float* __restrict__ W_ei,
    const float* __restrict__ W_ie,
    const float* __restrict__ W_ii,
    const float* __restrict__ W_inter)
{
    __shared__ float rs[NI + 8];       // inter needs 410, partial needs 256
    __shared__ float red[4];

    const int bx  = blockIdx.x;
    const int tid = threadIdx.x;

    if (bx < INTER_BLOCKS) {
        // ----------------- inter role -----------------
        const int a = bx % NI;
        const int i = bx / NI;

        const float* ri = r + (size_t)i * NU + NE;
        for (int b = tid; b < NI; b += 128) rs[b] = ri[b];
        __syncthreads();

        const float* base = W_inter + (size_t)i * N_NET * (NI * NI) + (size_t)a * NI;

        float acc = 0.f;
        for (int t = tid; t < NI / 2; t += 128) {
            const float x = rs[2 * t];
            const float y = rs[2 * t + 1];
            #pragma unroll 8
            for (int j = 0; j < N_NET; ++j) {
                const float2 w = *(const float2*)(base + (size_t)j * (NI * NI) + 2 * t);
                acc = fmaf(w.x, x, acc);
                acc = fmaf(w.y, y, acc);
            }
        }

        #pragma unroll
        for (int o = 16; o > 0; o >>= 1)
            acc += __shfl_down_sync(0xFFFFFFFFu, acc, o);
        if ((tid & 31) == 0) red[tid >> 5] = acc;
        __syncthreads();
        if (tid == 0)
            g_inter[i * NI + a] = red[0] + red[1] + red[2] + red[3];
    } else {
        // ----------------- partial GEMV role -----------------
        const int bx2 = bx - INTER_BLOCKS;
        const int qt  = bx2 & 15;          // q tile (16)
        const int ps  = (bx2 >> 4) & 7;    // p slice (8)
        const int n   = bx2 >> 7;          // net (32)

        const int q  = qt * 128 + tid;     // 0..2047
        const int pa = ps * P_PER_SLICE;
        const int pb = pa + P_PER_SLICE;

        rs[tid]       = r[(size_t)n * NU + pa + tid];
        rs[tid + 128] = r[(size_t)n * NU + pa + tid + 128];
        __syncthreads();

        const float* colE;
        const float* colI;
        int stride;
        if (q < NE) {
            stride = NE;
            colE = W_ee + (size_t)n * NE * NE + q;
            colI = W_ie + (size_t)n * NI * NE + q;
        } else {
            const int qq = q - NE;
            stride = NI;
            colE = W_ei + (size_t)n * NE * NI + qq;
            colI = W_ii + (size_t)n * NI * NI + qq;
        }

        float acc = 0.f;

        // rows p in [pa, min(pb, NE)) from the E-row matrix
        {
            const int pe = (pb < NE) ? pb : NE;
            int p = pa;
            for (; p + 8 <= pe; p += 8) {
                const float w0 = colE[(size_t)(p + 0) * stride];
                const float w1 = colE[(size_t)(p + 1) * stride];
                const float w2 = colE[(size_t)(p + 2) * stride];
                const float w3 = colE[(size_t)(p + 3) * stride];
                const float w4 = colE[(size_t)(p + 4) * stride];
                const float w5 = colE[(size_t)(p + 5) * stride];
                const float w6 = colE[(size_t)(p + 6) * stride];
                const float w7 = colE[(size_t)(p + 7) * stride];
                const int t = p - pa;
                acc = fmaf(w0, rs[t + 0], acc);
                acc = fmaf(w1, rs[t + 1], acc);
                acc = fmaf(w2, rs[t + 2], acc);
                acc = fmaf(w3, rs[t + 3], acc);
                acc = fmaf(w4, rs[t + 4], acc);
                acc = fmaf(w5, rs[t + 5], acc);
                acc = fmaf(w6, rs[t + 6], acc);
                acc = fmaf(w7, rs[t + 7], acc);
            }
            for (; p < pe; ++p)
                acc = fmaf(colE[(size_t)p * stride], rs[p - pa], acc);
        }

        // rows p in [max(pa, NE), pb) from the I-row matrix
        {
            const int p0 = (pa > NE) ? pa : NE;
            int p = p0;
            for (; p + 8 <= pb; p += 8) {
                const float w0 = colI[(size_t)(p - NE + 0) * stride];
                const float w1 = colI[(size_t)(p - NE + 1) * stride];
                const float w2 = colI[(size_t)(p - NE + 2) * stride];
                const float w3 = colI[(size_t)(p - NE + 3) * stride];
                const float w4 = colI[(size_t)(p - NE + 4) * stride];
                const float w5 = colI[(size_t)(p - NE + 5) * stride];
                const float w6 = colI[(size_t)(p - NE + 6) * stride];
                const float w7 = colI[(size_t)(p - NE + 7) * stride];
                const int t = p - pa;
                acc = fmaf(w0, rs[t + 0], acc);
                acc = fmaf(w1, rs[t + 1], acc);
                acc = fmaf(w2, rs[t + 2], acc);
                acc = fmaf(w3, rs[t + 3], acc);
                acc = fmaf(w4, rs[t + 4], acc);
                acc = fmaf(w5, rs[t + 5], acc);
                acc = fmaf(w6, rs[t + 6], acc);
                acc = fmaf(w7, rs[t + 7], acc);
            }
            for (; p < pb; ++p)
                acc = fmaf(colI[(size_t)(p - NE) * stride], rs[p - pa], acc);
        }

        g_partial[((size_t)ps * N_NET + n) * NU + q] = acc;
    }
}

// ---------------------------------------------------------------------------
// Reduce 8 partials + unit_input (+inter for inhibitory) + epilogue.
// ---------------------------------------------------------------------------
__global__ void __launch_bounds__(1024) reduce_kernel(
    const float* __restrict__ unit_input,
    const float* __restrict__ r,
    float* __restrict__ out)
{
    const int idx = blockIdx.x * 1024 + threadIdx.x;   // 0..65535
    const int n = idx >> 11;
    const int q = idx & 2047;

    float acc = 0.f;
    #pragma unroll
    for (int s = 0; s < P_SLICES; ++s)
        acc += g_partial[((size_t)s * N_NET + n) * NU + q];

    acc += unit_input[idx];
    if (q >= NE) acc += g_inter[n * NI + (q - NE)];

    const float rv  = r[idx];
    const float phi = fmaxf(acc, 0.f);
    out[idx] = rv + DT * ((phi - rv) / TAU);
}

extern "C" void kernel_launch(void* const* d_in, const int* in_sizes, int n_in,
                              void* d_out, int out_size)
{
    const float* unit_input = (const float*)d_in[0];
    const float* r          = (const float*)d_in[1];
    const float* W_ee       = (const float*)d_in[2];
    const float* W_ei       = (const float*)d_in[3];
    const float* W_ie       = (const float*)d_in[4];
    const float* W_ii       = (const float*)d_in[5];
    const float* W_inter    = (const float*)d_in[6];
    float* out = (float*)d_out;

    fused_kernel<<<TOTAL_BLOCKS, 128>>>(r, W_ee, W_ei, W_ie, W_ii, W_inter);
    reduce_kernel<<<64, 1024>>>(unit_input, r, out);
}